// round 8
// baseline (speedup 1.0000x reference)
#include <cuda_runtime.h>

#define NN 50000
#define EE 800000
#define DD 128

// ---------------- scratch (static __device__ arrays; no allocation) ----------------
__device__ __align__(16) float g_buf0[(size_t)NN * DD];
__device__ __align__(16) float g_buf1[(size_t)NN * DD];
__device__ float g_outnorm[NN];
__device__ float g_innorm [NN];
__device__ int   g_indeg  [NN];
__device__ int   g_outdeg [NN];
__device__ int   g_cursor [NN];
__device__ int   g_rowptr [NN + 1];
__device__ int   g_srcsorted[EE];

#define SCAN_T 512
#define SCAN_I 4
#define SCAN_CHUNK (SCAN_T * SCAN_I)                       // 2048
#define SCAN_B ((NN + SCAN_CHUNK - 1) / SCAN_CHUNK)        // 25
__device__ int g_blockSums[SCAN_B];
__device__ int g_blockOffs[SCAN_B];

// ---------------- f32x2 packed-FMA helpers (FFMA2 — only reachable via PTX) -------
__device__ __forceinline__ unsigned long long pack2(float x, float y) {
    unsigned long long r;
    asm("mov.b64 %0, {%1, %2};" : "=l"(r) : "f"(x), "f"(y));
    return r;
}
__device__ __forceinline__ unsigned long long bcast2(float x) {
    unsigned long long r;
    asm("mov.b64 %0, {%1, %1};" : "=l"(r) : "f"(x));
    return r;
}
__device__ __forceinline__ void ffma2(unsigned long long& d,
                                      unsigned long long a, unsigned long long b) {
    asm("fma.rn.f32x2 %0, %1, %2, %0;" : "+l"(d) : "l"(a), "l"(b));
}
__device__ __forceinline__ void unpack2(unsigned long long v, float& x, float& y) {
    asm("mov.b64 {%0, %1}, %2;" : "=f"(x), "=f"(y) : "l"(v));
}

// ---------------- graph preprocessing ----------------
__global__ void zero_kernel() {
    int i = blockIdx.x * blockDim.x + threadIdx.x;
    if (i < NN) { g_indeg[i] = 0; g_outdeg[i] = 0; g_cursor[i] = 0; }
}

__global__ void deg_kernel(const int* __restrict__ src, const int* __restrict__ dst) {
    int i = blockIdx.x * blockDim.x + threadIdx.x;
    if (i < EE) {
        atomicAdd(&g_outdeg[src[i]], 1);
        atomicAdd(&g_indeg [dst[i]], 1);
    }
}

__global__ void norm_kernel() {
    int i = blockIdx.x * blockDim.x + threadIdx.x;
    if (i < NN) {
        g_outnorm[i] = rsqrtf(fmaxf((float)g_outdeg[i], 1.0f));
        g_innorm [i] = rsqrtf(fmaxf((float)g_indeg [i], 1.0f));
    }
}

// ---- two-level scan ----
__global__ void scanA_kernel() {
    __shared__ int warpSums[SCAN_T / 32];
    int b   = blockIdx.x;
    int tid = threadIdx.x;
    int lane = tid & 31, wid = tid >> 5;
    int base = b * SCAN_CHUNK + tid * SCAN_I;

    int v[SCAN_I];
    int s = 0;
    #pragma unroll
    for (int j = 0; j < SCAN_I; j++) {
        int i = base + j;
        v[j] = (i < NN) ? g_indeg[i] : 0;
        s += v[j];
    }
    int incl = s;
    #pragma unroll
    for (int off = 1; off < 32; off <<= 1) {
        int t = __shfl_up_sync(0xffffffff, incl, off);
        if (lane >= off) incl += t;
    }
    if (lane == 31) warpSums[wid] = incl;
    __syncthreads();
    if (wid == 0) {
        int ws = (lane < SCAN_T / 32) ? warpSums[lane] : 0;
        #pragma unroll
        for (int off = 1; off < SCAN_T / 32; off <<= 1) {
            int t = __shfl_up_sync(0xffffffff, ws, off);
            if (lane >= off) ws += t;
        }
        if (lane < SCAN_T / 32) warpSums[lane] = ws;
    }
    __syncthreads();
    int warpOff = (wid > 0) ? warpSums[wid - 1] : 0;
    int run     = warpOff + incl - s;
    #pragma unroll
    for (int j = 0; j < SCAN_I; j++) {
        int i = base + j;
        if (i < NN) g_rowptr[i] = run;
        run += v[j];
    }
    if (tid == SCAN_T - 1) g_blockSums[b] = warpSums[SCAN_T / 32 - 1];
}

__global__ void scanB_kernel() {
    int lane = threadIdx.x;
    int v = (lane < SCAN_B) ? g_blockSums[lane] : 0;
    int incl = v;
    #pragma unroll
    for (int off = 1; off < 32; off <<= 1) {
        int t = __shfl_up_sync(0xffffffff, incl, off);
        if (lane >= off) incl += t;
    }
    if (lane < SCAN_B) g_blockOffs[lane] = incl - v;
    if (lane == 31) g_rowptr[NN] = incl;
}

__global__ void scanC_kernel() {
    int b = blockIdx.x;
    int off = g_blockOffs[b];
    if (off == 0) return;
    int base = b * SCAN_CHUNK + threadIdx.x * SCAN_I;
    #pragma unroll
    for (int j = 0; j < SCAN_I; j++) {
        int i = base + j;
        if (i < NN) g_rowptr[i] += off;
    }
}

__global__ void scatter_kernel(const int* __restrict__ src, const int* __restrict__ dst) {
    int i = blockIdx.x * blockDim.x + threadIdx.x;
    if (i < EE) {
        int d = dst[i];
        int pos = g_rowptr[d] + atomicAdd(&g_cursor[d], 1);
        g_srcsorted[pos] = src[i];
    }
}

// ---------------- fused layer: aggregate 128 nodes into smem, then GEMM ----------------
// C[M,128] = (in_norm * Agg(out_norm * h))[M,128] @ W[128,128] + b, optional relu
#define LDH 132   // Hs row pitch (floats): 528B, 16B-aligned, conflict-free f4 stores

__global__ void fused_kernel(const float* __restrict__ h, const float* __restrict__ W,
                             const float* __restrict__ bias, float* __restrict__ C,
                             int doRelu) {
    extern __shared__ float smem[];
    float* Hs = smem;               // row-major: Hs[m*LDH + k], 128 x 132
    float* Bs = smem + 128 * LDH;   // row-major: Bs[k*128 + n], 128 x 128
    int tid = threadIdx.x;
    int lane = tid & 31, w = tid >> 5;   // 8 warps
    int blockM = blockIdx.x * 128;

    // ---- load W tile (all 256 threads, coalesced) ----
    {
        int nq = tid & 31;
        int kg = tid >> 5;
        #pragma unroll
        for (int r = 0; r < 16; r++) {
            int k = kg * 16 + r;
            *(float4*)(Bs + k * 128 + nq * 4) = *(const float4*)(W + k * 128 + nq * 4);
        }
    }

    // ---- phase 1: gather/aggregate — warp w handles nodes [w*16, w*16+16) ----
    #pragma unroll 1
    for (int i = 0; i < 16; i++) {
        int m  = w * 16 + i;
        int gm = blockM + m;
        if (gm >= NN) break;
        int beg = g_rowptr[gm], end = g_rowptr[gm + 1];

        float ax = 0.f, ay = 0.f, az = 0.f, aw = 0.f;
        int e = beg;
        for (; e + 4 <= end; e += 4) {
            int s0 = g_srcsorted[e],     s1 = g_srcsorted[e + 1];
            int s2 = g_srcsorted[e + 2], s3 = g_srcsorted[e + 3];
            float w0 = g_outnorm[s0], w1 = g_outnorm[s1];
            float w2 = g_outnorm[s2], w3 = g_outnorm[s3];
            float4 x0 = *(const float4*)(h + (size_t)s0 * DD + lane * 4);
            float4 x1 = *(const float4*)(h + (size_t)s1 * DD + lane * 4);
            float4 x2 = *(const float4*)(h + (size_t)s2 * DD + lane * 4);
            float4 x3 = *(const float4*)(h + (size_t)s3 * DD + lane * 4);
            ax += w0 * x0.x; ay += w0 * x0.y; az += w0 * x0.z; aw += w0 * x0.w;
            ax += w1 * x1.x; ay += w1 * x1.y; az += w1 * x1.z; aw += w1 * x1.w;
            ax += w2 * x2.x; ay += w2 * x2.y; az += w2 * x2.z; aw += w2 * x2.w;
            ax += w3 * x3.x; ay += w3 * x3.y; az += w3 * x3.z; aw += w3 * x3.w;
        }
        for (; e < end; e++) {
            int s0 = g_srcsorted[e];
            float w0 = g_outnorm[s0];
            float4 x0 = *(const float4*)(h + (size_t)s0 * DD + lane * 4);
            ax += w0 * x0.x; ay += w0 * x0.y; az += w0 * x0.z; aw += w0 * x0.w;
        }
        float s = g_innorm[gm];
        *(float4*)(Hs + m * LDH + lane * 4) = make_float4(ax * s, ay * s, az * s, aw * s);
    }
    __syncthreads();

    // ---- phase 2: GEMM from smem (8x8 per thread, packed f32x2 FMA) ----
    int tx = tid & 15, ty = tid >> 4;
    int mBase = ty * 8, nBase = tx * 8;

    unsigned long long acc[8][4];
    const unsigned long long z = pack2(0.f, 0.f);
    #pragma unroll
    for (int i = 0; i < 8; i++)
        #pragma unroll
        for (int jp = 0; jp < 4; jp++) acc[i][jp] = z;

    #pragma unroll 4
    for (int k = 0; k < 128; k++) {
        float4 b0 = *(const float4*)(Bs + k * 128 + nBase);
        float4 b1 = *(const float4*)(Bs + k * 128 + nBase + 4);
        unsigned long long bp[4];
        bp[0] = pack2(b0.x, b0.y);
        bp[1] = pack2(b0.z, b0.w);
        bp[2] = pack2(b1.x, b1.y);
        bp[3] = pack2(b1.z, b1.w);

        #pragma unroll
        for (int i = 0; i < 8; i++) {
            unsigned long long aa = bcast2(Hs[(mBase + i) * LDH + k]);
            #pragma unroll
            for (int jp = 0; jp < 4; jp++)
                ffma2(acc[i][jp], aa, bp[jp]);
        }
    }

    float bv[8];
    #pragma unroll
    for (int j = 0; j < 8; j++) bv[j] = bias[nBase + j];

    #pragma unroll
    for (int i = 0; i < 8; i++) {
        int gm = blockM + mBase + i;
        if (gm < NN) {
            float o[8];
            #pragma unroll
            for (int jp = 0; jp < 4; jp++) {
                float x, y;
                unpack2(acc[i][jp], x, y);
                o[jp * 2]     = x + bv[jp * 2];
                o[jp * 2 + 1] = y + bv[jp * 2 + 1];
            }
            if (doRelu) {
                #pragma unroll
                for (int j = 0; j < 8; j++) o[j] = fmaxf(o[j], 0.f);
            }
            *(float4*)(C + (size_t)gm * DD + nBase)     = make_float4(o[0], o[1], o[2], o[3]);
            *(float4*)(C + (size_t)gm * DD + nBase + 4) = make_float4(o[4], o[5], o[6], o[7]);
        }
    }
}

// ---------------- launch ----------------
extern "C" void kernel_launch(void* const* d_in, const int* in_sizes, int n_in,
                              void* d_out, int out_size) {
    const float* h   = (const float*)d_in[0];
    const float* e   = (const float*)d_in[1];
    const int*   src = (const int*)  d_in[2];
    const int*   dst = (const int*)  d_in[3];
    const float* Ws  = (const float*)d_in[4];
    const float* bs  = (const float*)d_in[5];
    float* out = (float*)d_out;

    // Side stream + events: e-passthrough copy runs parallel to the compute chain.
    static cudaStream_t s_side = nullptr;
    static cudaEvent_t  s_fork = nullptr, s_join = nullptr;
    if (!s_side) {
        cudaStreamCreateWithFlags(&s_side, cudaStreamNonBlocking);
        cudaEventCreateWithFlags(&s_fork, cudaEventDisableTiming);
        cudaEventCreateWithFlags(&s_join, cudaEventDisableTiming);
    }

    size_t eElems = (size_t)in_sizes[1];
    bool overlapped = false;
    if (s_side && s_fork && s_join) {
        if (cudaEventRecord(s_fork, 0) == cudaSuccess &&
            cudaStreamWaitEvent(s_side, s_fork, 0) == cudaSuccess) {
            cudaMemcpyAsync(out + (size_t)NN * DD, e, eElems * sizeof(float),
                            cudaMemcpyDeviceToDevice, s_side);
            cudaEventRecord(s_join, s_side);
            overlapped = true;
        }
    }
    if (!overlapped) {
        cudaMemcpyAsync(out + (size_t)NN * DD, e, eElems * sizeof(float),
                        cudaMemcpyDeviceToDevice);
    }

    const int nb = (NN + 255) / 256;
    const int eb = (EE + 255) / 256;
    zero_kernel<<<nb, 256>>>();
    deg_kernel<<<eb, 256>>>(src, dst);
    norm_kernel<<<nb, 256>>>();
    scanA_kernel<<<SCAN_B, SCAN_T>>>();
    scanB_kernel<<<1, 32>>>();
    scanC_kernel<<<SCAN_B, SCAN_T>>>();
    scatter_kernel<<<eb, 256>>>(src, dst);

    float *b0, *b1;
    cudaGetSymbolAddress((void**)&b0, g_buf0);
    cudaGetSymbolAddress((void**)&b1, g_buf1);

    const int SMEM = (128 * LDH + 128 * 128) * (int)sizeof(float);
    cudaFuncSetAttribute(fused_kernel, cudaFuncAttributeMaxDynamicSharedMemorySize, SMEM);

    const int blocks = (NN + 127) / 128;

    fused_kernel<<<blocks, 256, SMEM>>>(h,  Ws,               bs,          b0, 1);
    fused_kernel<<<blocks, 256, SMEM>>>(b0, Ws + DD * DD,     bs + DD,     b1, 1);
    fused_kernel<<<blocks, 256, SMEM>>>(b1, Ws + 2 * DD * DD, bs + 2 * DD, out, 0);

    if (overlapped) cudaStreamWaitEvent(0, s_join, 0);
}

// round 9
// speedup vs baseline: 1.4466x; 1.4466x over previous
#include <cuda_runtime.h>

#define NN 50000
#define EE 800000
#define DD 128

// ---------------- scratch (static __device__ arrays; no allocation) ----------------
__device__ __align__(16) float g_agg [(size_t)NN * DD];
__device__ __align__(16) float g_buf0[(size_t)NN * DD];
__device__ __align__(16) float g_buf1[(size_t)NN * DD];
__device__ float g_outnorm[NN];
__device__ float g_innorm [NN];
__device__ int   g_indeg  [NN];
__device__ int   g_outdeg [NN];
__device__ int   g_cursor [NN];
__device__ int   g_rowptr [NN + 1];
__device__ int   g_srcsorted[EE];

#define SCAN_T 512
#define SCAN_I 4
#define SCAN_CHUNK (SCAN_T * SCAN_I)                       // 2048
#define SCAN_B ((NN + SCAN_CHUNK - 1) / SCAN_CHUNK)        // 25
__device__ int g_blockSums[SCAN_B];
__device__ int g_blockOffs[SCAN_B];

// ---------------- f32x2 packed-FMA helpers ----------------
__device__ __forceinline__ unsigned long long pack2(float x, float y) {
    unsigned long long r;
    asm("mov.b64 %0, {%1, %2};" : "=l"(r) : "f"(x), "f"(y));
    return r;
}
__device__ __forceinline__ unsigned long long bcast2(float x) {
    unsigned long long r;
    asm("mov.b64 %0, {%1, %1};" : "=l"(r) : "f"(x));
    return r;
}
__device__ __forceinline__ void ffma2(unsigned long long& d,
                                      unsigned long long a, unsigned long long b) {
    asm("fma.rn.f32x2 %0, %1, %2, %0;" : "+l"(d) : "l"(a), "l"(b));
}
__device__ __forceinline__ void unpack2(unsigned long long v, float& x, float& y) {
    asm("mov.b64 {%0, %1}, %2;" : "=f"(x), "=f"(y) : "l"(v));
}

// ---------------- streaming passthrough copy (evict-first: no L2 pollution) --------
__global__ void copy_kernel(const float4* __restrict__ src, float4* __restrict__ dst,
                            int n4) {
    int i = blockIdx.x * blockDim.x + threadIdx.x;
    int stride = gridDim.x * blockDim.x;
    // 4-way unrolled grid-stride for MLP
    int i3 = i + 3 * stride;
    for (; i3 < n4; i += 4 * stride, i3 += 4 * stride) {
        float4 v0 = __ldcs(src + i);
        float4 v1 = __ldcs(src + i + stride);
        float4 v2 = __ldcs(src + i + 2 * stride);
        float4 v3 = __ldcs(src + i + 3 * stride);
        __stcs(dst + i,              v0);
        __stcs(dst + i + stride,     v1);
        __stcs(dst + i + 2 * stride, v2);
        __stcs(dst + i + 3 * stride, v3);
    }
    for (; i < n4; i += stride) {
        __stcs(dst + i, __ldcs(src + i));
    }
}

// ---------------- graph preprocessing ----------------
__global__ void zero_kernel() {
    int i = blockIdx.x * blockDim.x + threadIdx.x;
    if (i < NN) { g_indeg[i] = 0; g_outdeg[i] = 0; g_cursor[i] = 0; }
}

__global__ void deg_kernel(const int* __restrict__ src, const int* __restrict__ dst) {
    int i = blockIdx.x * blockDim.x + threadIdx.x;
    if (i < EE) {
        atomicAdd(&g_outdeg[src[i]], 1);
        atomicAdd(&g_indeg [dst[i]], 1);
    }
}

__global__ void norm_kernel() {
    int i = blockIdx.x * blockDim.x + threadIdx.x;
    if (i < NN) {
        g_outnorm[i] = rsqrtf(fmaxf((float)g_outdeg[i], 1.0f));
        g_innorm [i] = rsqrtf(fmaxf((float)g_indeg [i], 1.0f));
    }
}

// ---- two-level scan ----
__global__ void scanA_kernel() {
    __shared__ int warpSums[SCAN_T / 32];
    int b   = blockIdx.x;
    int tid = threadIdx.x;
    int lane = tid & 31, wid = tid >> 5;
    int base = b * SCAN_CHUNK + tid * SCAN_I;

    int v[SCAN_I];
    int s = 0;
    #pragma unroll
    for (int j = 0; j < SCAN_I; j++) {
        int i = base + j;
        v[j] = (i < NN) ? g_indeg[i] : 0;
        s += v[j];
    }
    int incl = s;
    #pragma unroll
    for (int off = 1; off < 32; off <<= 1) {
        int t = __shfl_up_sync(0xffffffff, incl, off);
        if (lane >= off) incl += t;
    }
    if (lane == 31) warpSums[wid] = incl;
    __syncthreads();
    if (wid == 0) {
        int ws = (lane < SCAN_T / 32) ? warpSums[lane] : 0;
        #pragma unroll
        for (int off = 1; off < SCAN_T / 32; off <<= 1) {
            int t = __shfl_up_sync(0xffffffff, ws, off);
            if (lane >= off) ws += t;
        }
        if (lane < SCAN_T / 32) warpSums[lane] = ws;
    }
    __syncthreads();
    int warpOff = (wid > 0) ? warpSums[wid - 1] : 0;
    int run     = warpOff + incl - s;
    #pragma unroll
    for (int j = 0; j < SCAN_I; j++) {
        int i = base + j;
        if (i < NN) g_rowptr[i] = run;
        run += v[j];
    }
    if (tid == SCAN_T - 1) g_blockSums[b] = warpSums[SCAN_T / 32 - 1];
}

__global__ void scanB_kernel() {
    int lane = threadIdx.x;
    int v = (lane < SCAN_B) ? g_blockSums[lane] : 0;
    int incl = v;
    #pragma unroll
    for (int off = 1; off < 32; off <<= 1) {
        int t = __shfl_up_sync(0xffffffff, incl, off);
        if (lane >= off) incl += t;
    }
    if (lane < SCAN_B) g_blockOffs[lane] = incl - v;
    if (lane == 31) g_rowptr[NN] = incl;
}

__global__ void scanC_kernel() {
    int b = blockIdx.x;
    int off = g_blockOffs[b];
    if (off == 0) return;
    int base = b * SCAN_CHUNK + threadIdx.x * SCAN_I;
    #pragma unroll
    for (int j = 0; j < SCAN_I; j++) {
        int i = base + j;
        if (i < NN) g_rowptr[i] += off;
    }
}

__global__ void scatter_kernel(const int* __restrict__ src, const int* __restrict__ dst) {
    int i = blockIdx.x * blockDim.x + threadIdx.x;
    if (i < EE) {
        int d = dst[i];
        int pos = g_rowptr[d] + atomicAdd(&g_cursor[d], 1);
        g_srcsorted[pos] = src[i];
    }
}

// ---------------- aggregation: one warp per node, CSR, no float atomics ----------------
__global__ void agg_kernel(const float* __restrict__ h) {
    int gw = (blockIdx.x * blockDim.x + threadIdx.x) >> 5;
    if (gw >= NN) return;
    int lane = threadIdx.x & 31;
    int beg = g_rowptr[gw], end = g_rowptr[gw + 1];

    float ax = 0.f, ay = 0.f, az = 0.f, aw = 0.f;
    int e = beg;
    for (; e + 2 <= end; e += 2) {
        int s0 = g_srcsorted[e], s1 = g_srcsorted[e + 1];
        float w0 = g_outnorm[s0], w1 = g_outnorm[s1];
        float4 x0 = *(const float4*)(h + (size_t)s0 * DD + lane * 4);
        float4 x1 = *(const float4*)(h + (size_t)s1 * DD + lane * 4);
        ax += w0 * x0.x; ay += w0 * x0.y; az += w0 * x0.z; aw += w0 * x0.w;
        ax += w1 * x1.x; ay += w1 * x1.y; az += w1 * x1.z; aw += w1 * x1.w;
    }
    if (e < end) {
        int s0 = g_srcsorted[e];
        float w0 = g_outnorm[s0];
        float4 x0 = *(const float4*)(h + (size_t)s0 * DD + lane * 4);
        ax += w0 * x0.x; ay += w0 * x0.y; az += w0 * x0.z; aw += w0 * x0.w;
    }
    float s = g_innorm[gw];
    float4 r = make_float4(ax * s, ay * s, az * s, aw * s);
    *(float4*)(g_agg + (size_t)gw * DD + lane * 4) = r;
}

// ---------------- SGEMM: C[M,128] = A[M,128] @ W[128,128] + b, optional relu ----------
#define LDSA 132

__global__ void gemm_kernel(const float* __restrict__ A, const float* __restrict__ W,
                            const float* __restrict__ bias, float* __restrict__ C,
                            int M, int doRelu) {
    extern __shared__ float smem[];
    float* As = smem;               // k-major: As[k*LDSA + m]
    float* Bs = smem + 128 * LDSA;  // row-major: Bs[k*128 + n]
    int tid = threadIdx.x;
    int blockM = blockIdx.x * 128;

    {
        int m  = tid >> 1;
        int kh = (tid & 1) * 64;
        int gm = blockM + m;
        bool valid = gm < M;
        const float4* arow = (const float4*)(A + (size_t)gm * DD + kh);
        #pragma unroll
        for (int j = 0; j < 16; j++) {
            float4 v = valid ? arow[j] : make_float4(0.f, 0.f, 0.f, 0.f);
            int k = kh + j * 4;
            As[(k + 0) * LDSA + m] = v.x;
            As[(k + 1) * LDSA + m] = v.y;
            As[(k + 2) * LDSA + m] = v.z;
            As[(k + 3) * LDSA + m] = v.w;
        }
    }
    {
        int nq = tid & 31;
        int kg = tid >> 5;
        #pragma unroll
        for (int r = 0; r < 16; r++) {
            int k = kg * 16 + r;
            *(float4*)(Bs + k * 128 + nq * 4) = *(const float4*)(W + k * 128 + nq * 4);
        }
    }
    __syncthreads();

    int tx = tid & 15, ty = tid >> 4;
    int mBase = ty * 8, nBase = tx * 8;

    unsigned long long acc[8][4];
    const unsigned long long z = pack2(0.f, 0.f);
    #pragma unroll
    for (int i = 0; i < 8; i++)
        #pragma unroll
        for (int jp = 0; jp < 4; jp++) acc[i][jp] = z;

    #pragma unroll 4
    for (int k = 0; k < 128; k++) {
        float4 a0 = *(const float4*)(As + k * LDSA + mBase);
        float4 a1 = *(const float4*)(As + k * LDSA + mBase + 4);
        float4 b0 = *(const float4*)(Bs + k * 128 + nBase);
        float4 b1 = *(const float4*)(Bs + k * 128 + nBase + 4);

        unsigned long long bp[4];
        bp[0] = pack2(b0.x, b0.y);
        bp[1] = pack2(b0.z, b0.w);
        bp[2] = pack2(b1.x, b1.y);
        bp[3] = pack2(b1.z, b1.w);

        float a[8] = {a0.x, a0.y, a0.z, a0.w, a1.x, a1.y, a1.z, a1.w};
        #pragma unroll
        for (int i = 0; i < 8; i++) {
            unsigned long long aa = bcast2(a[i]);
            #pragma unroll
            for (int jp = 0; jp < 4; jp++)
                ffma2(acc[i][jp], aa, bp[jp]);
        }
    }

    float bv[8];
    #pragma unroll
    for (int j = 0; j < 8; j++) bv[j] = bias[nBase + j];

    #pragma unroll
    for (int i = 0; i < 8; i++) {
        int gm = blockM + mBase + i;
        if (gm < M) {
            float o[8];
            #pragma unroll
            for (int jp = 0; jp < 4; jp++) {
                float x, y;
                unpack2(acc[i][jp], x, y);
                o[jp * 2]     = x + bv[jp * 2];
                o[jp * 2 + 1] = y + bv[jp * 2 + 1];
            }
            if (doRelu) {
                #pragma unroll
                for (int j = 0; j < 8; j++) o[j] = fmaxf(o[j], 0.f);
            }
            *(float4*)(C + (size_t)gm * DD + nBase)     = make_float4(o[0], o[1], o[2], o[3]);
            *(float4*)(C + (size_t)gm * DD + nBase + 4) = make_float4(o[4], o[5], o[6], o[7]);
        }
    }
}

// ---------------- launch ----------------
extern "C" void kernel_launch(void* const* d_in, const int* in_sizes, int n_in,
                              void* d_out, int out_size) {
    const float* h   = (const float*)d_in[0];
    const float* e   = (const float*)d_in[1];
    const int*   src = (const int*)  d_in[2];
    const int*   dst = (const int*)  d_in[3];
    const float* Ws  = (const float*)d_in[4];
    const float* bs  = (const float*)d_in[5];
    float* out = (float*)d_out;

    // Side stream + events: streaming copy kernel runs parallel to compute.
    static cudaStream_t s_side = nullptr;
    static cudaEvent_t  s_fork = nullptr, s_join = nullptr;
    if (!s_side) {
        cudaStreamCreateWithFlags(&s_side, cudaStreamNonBlocking);
        cudaEventCreateWithFlags(&s_fork, cudaEventDisableTiming);
        cudaEventCreateWithFlags(&s_join, cudaEventDisableTiming);
    }

    size_t eElems = (size_t)in_sizes[1];
    int n4 = (int)(eElems / 4);          // E*D divisible by 4
    const int copyBlocks = 148 * 6;
    bool overlapped = false;
    if (s_side && s_fork && s_join) {
        if (cudaEventRecord(s_fork, 0) == cudaSuccess &&
            cudaStreamWaitEvent(s_side, s_fork, 0) == cudaSuccess) {
            copy_kernel<<<copyBlocks, 256, 0, s_side>>>(
                (const float4*)e, (float4*)(out + (size_t)NN * DD), n4);
            cudaEventRecord(s_join, s_side);
            overlapped = true;
        }
    }
    if (!overlapped) {
        copy_kernel<<<copyBlocks, 256>>>(
            (const float4*)e, (float4*)(out + (size_t)NN * DD), n4);
    }

    const int nb = (NN + 255) / 256;
    const int eb = (EE + 255) / 256;
    zero_kernel<<<nb, 256>>>();
    deg_kernel<<<eb, 256>>>(src, dst);
    norm_kernel<<<nb, 256>>>();
    scanA_kernel<<<SCAN_B, SCAN_T>>>();
    scanB_kernel<<<1, 32>>>();
    scanC_kernel<<<SCAN_B, SCAN_T>>>();
    scatter_kernel<<<eb, 256>>>(src, dst);

    float *agg, *b0, *b1;
    cudaGetSymbolAddress((void**)&agg, g_agg);
    cudaGetSymbolAddress((void**)&b0,  g_buf0);
    cudaGetSymbolAddress((void**)&b1,  g_buf1);

    const int SMEM = (128 * LDSA + 128 * 128) * (int)sizeof(float);
    cudaFuncSetAttribute(gemm_kernel, cudaFuncAttributeMaxDynamicSharedMemorySize, SMEM);

    const int aggBlocks  = (NN * 32 + 255) / 256;
    const int gemmBlocks = (NN + 127) / 128;

    // layer 0
    agg_kernel<<<aggBlocks, 256>>>(h);
    gemm_kernel<<<gemmBlocks, 256, SMEM>>>(agg, Ws,               bs,          b0, NN, 1);
    // layer 1
    agg_kernel<<<aggBlocks, 256>>>(b0);
    gemm_kernel<<<gemmBlocks, 256, SMEM>>>(agg, Ws + DD * DD,     bs + DD,     b1, NN, 1);
    // layer 2 (no relu), write straight into d_out
    agg_kernel<<<aggBlocks, 256>>>(b1);
    gemm_kernel<<<gemmBlocks, 256, SMEM>>>(agg, Ws + 2 * DD * DD, bs + 2 * DD, out, NN, 0);

    if (overlapped) cudaStreamWaitEvent(0, s_join, 0);
}

// round 10
// speedup vs baseline: 1.5111x; 1.0446x over previous
#include <cuda_runtime.h>

#define NN 50000
#define EE 800000
#define DD 128

// ---------------- scratch (static __device__ arrays; no allocation) ----------------
__device__ __align__(16) float g_agg [(size_t)NN * DD];
__device__ __align__(16) float g_buf0[(size_t)NN * DD];
__device__ __align__(16) float g_buf1[(size_t)NN * DD];
__device__ float g_outnorm[NN];
__device__ float g_innorm [NN];
__device__ int   g_indeg  [NN];
__device__ int   g_outdeg [NN];
__device__ int   g_cursor [NN];
__device__ int   g_rowptr [NN + 1];
__device__ int   g_srcsorted[EE];

#define SCAN_T 512
#define SCAN_I 4
#define SCAN_CHUNK (SCAN_T * SCAN_I)                       // 2048
#define SCAN_B ((NN + SCAN_CHUNK - 1) / SCAN_CHUNK)        // 25
__device__ int g_blockSums[SCAN_B];
__device__ int g_blockOffs[SCAN_B];

// ---------------- f32x2 packed-FMA helpers ----------------
__device__ __forceinline__ unsigned long long pack2(float x, float y) {
    unsigned long long r;
    asm("mov.b64 %0, {%1, %2};" : "=l"(r) : "f"(x), "f"(y));
    return r;
}
__device__ __forceinline__ unsigned long long bcast2(float x) {
    unsigned long long r;
    asm("mov.b64 %0, {%1, %1};" : "=l"(r) : "f"(x));
    return r;
}
__device__ __forceinline__ void ffma2(unsigned long long& d,
                                      unsigned long long a, unsigned long long b) {
    asm("fma.rn.f32x2 %0, %1, %2, %0;" : "+l"(d) : "l"(a), "l"(b));
}
__device__ __forceinline__ void unpack2(unsigned long long v, float& x, float& y) {
    asm("mov.b64 {%0, %1}, %2;" : "=f"(x), "=f"(y) : "l"(v));
}

// ---------------- thin streaming copy: 1 block/SM, deep MLP, evict-first ----------
#define CPY_UNROLL 16
__global__ void copy_kernel(const float4* __restrict__ src, float4* __restrict__ dst,
                            int n4) {
    int stride = gridDim.x * blockDim.x;
    int i = blockIdx.x * blockDim.x + threadIdx.x;
    int span = stride * CPY_UNROLL;
    // main: 16 loads in flight per thread
    for (; i + (CPY_UNROLL - 1) * stride < n4; i += span) {
        float4 v[CPY_UNROLL];
        #pragma unroll
        for (int u = 0; u < CPY_UNROLL; u++) v[u] = __ldcs(src + i + u * stride);
        #pragma unroll
        for (int u = 0; u < CPY_UNROLL; u++) __stcs(dst + i + u * stride, v[u]);
    }
    for (; i < n4; i += stride) __stcs(dst + i, __ldcs(src + i));
}

// ---------------- graph preprocessing ----------------
__global__ void zero_kernel() {
    int i = blockIdx.x * blockDim.x + threadIdx.x;
    if (i < NN) { g_indeg[i] = 0; g_outdeg[i] = 0; g_cursor[i] = 0; }
}

__global__ void deg_kernel(const int* __restrict__ src, const int* __restrict__ dst) {
    int i = blockIdx.x * blockDim.x + threadIdx.x;
    if (i < EE) {
        atomicAdd(&g_outdeg[src[i]], 1);
        atomicAdd(&g_indeg [dst[i]], 1);
    }
}

__global__ void norm_kernel() {
    int i = blockIdx.x * blockDim.x + threadIdx.x;
    if (i < NN) {
        g_outnorm[i] = rsqrtf(fmaxf((float)g_outdeg[i], 1.0f));
        g_innorm [i] = rsqrtf(fmaxf((float)g_indeg [i], 1.0f));
    }
}

// ---- two-level scan ----
__global__ void scanA_kernel() {
    __shared__ int warpSums[SCAN_T / 32];
    int b   = blockIdx.x;
    int tid = threadIdx.x;
    int lane = tid & 31, wid = tid >> 5;
    int base = b * SCAN_CHUNK + tid * SCAN_I;

    int v[SCAN_I];
    int s = 0;
    #pragma unroll
    for (int j = 0; j < SCAN_I; j++) {
        int i = base + j;
        v[j] = (i < NN) ? g_indeg[i] : 0;
        s += v[j];
    }
    int incl = s;
    #pragma unroll
    for (int off = 1; off < 32; off <<= 1) {
        int t = __shfl_up_sync(0xffffffff, incl, off);
        if (lane >= off) incl += t;
    }
    if (lane == 31) warpSums[wid] = incl;
    __syncthreads();
    if (wid == 0) {
        int ws = (lane < SCAN_T / 32) ? warpSums[lane] : 0;
        #pragma unroll
        for (int off = 1; off < SCAN_T / 32; off <<= 1) {
            int t = __shfl_up_sync(0xffffffff, ws, off);
            if (lane >= off) ws += t;
        }
        if (lane < SCAN_T / 32) warpSums[lane] = ws;
    }
    __syncthreads();
    int warpOff = (wid > 0) ? warpSums[wid - 1] : 0;
    int run     = warpOff + incl - s;
    #pragma unroll
    for (int j = 0; j < SCAN_I; j++) {
        int i = base + j;
        if (i < NN) g_rowptr[i] = run;
        run += v[j];
    }
    if (tid == SCAN_T - 1) g_blockSums[b] = warpSums[SCAN_T / 32 - 1];
}

__global__ void scanB_kernel() {
    int lane = threadIdx.x;
    int v = (lane < SCAN_B) ? g_blockSums[lane] : 0;
    int incl = v;
    #pragma unroll
    for (int off = 1; off < 32; off <<= 1) {
        int t = __shfl_up_sync(0xffffffff, incl, off);
        if (lane >= off) incl += t;
    }
    if (lane < SCAN_B) g_blockOffs[lane] = incl - v;
    if (lane == 31) g_rowptr[NN] = incl;
}

__global__ void scanC_kernel() {
    int b = blockIdx.x;
    int off = g_blockOffs[b];
    if (off == 0) return;
    int base = b * SCAN_CHUNK + threadIdx.x * SCAN_I;
    #pragma unroll
    for (int j = 0; j < SCAN_I; j++) {
        int i = base + j;
        if (i < NN) g_rowptr[i] += off;
    }
}

__global__ void scatter_kernel(const int* __restrict__ src, const int* __restrict__ dst) {
    int i = blockIdx.x * blockDim.x + threadIdx.x;
    if (i < EE) {
        int d = dst[i];
        int pos = g_rowptr[d] + atomicAdd(&g_cursor[d], 1);
        g_srcsorted[pos] = src[i];
    }
}

// ---------------- aggregation: one warp per node, CSR, 4-way unrolled ----------------
__global__ void agg_kernel(const float* __restrict__ h) {
    int gw = (blockIdx.x * blockDim.x + threadIdx.x) >> 5;
    if (gw >= NN) return;
    int lane = threadIdx.x & 31;
    int beg = g_rowptr[gw], end = g_rowptr[gw + 1];

    float ax = 0.f, ay = 0.f, az = 0.f, aw = 0.f;
    int e = beg;
    for (; e + 4 <= end; e += 4) {
        int s0 = g_srcsorted[e],     s1 = g_srcsorted[e + 1];
        int s2 = g_srcsorted[e + 2], s3 = g_srcsorted[e + 3];
        float w0 = g_outnorm[s0], w1 = g_outnorm[s1];
        float w2 = g_outnorm[s2], w3 = g_outnorm[s3];
        float4 x0 = *(const float4*)(h + (size_t)s0 * DD + lane * 4);
        float4 x1 = *(const float4*)(h + (size_t)s1 * DD + lane * 4);
        float4 x2 = *(const float4*)(h + (size_t)s2 * DD + lane * 4);
        float4 x3 = *(const float4*)(h + (size_t)s3 * DD + lane * 4);
        ax += w0 * x0.x; ay += w0 * x0.y; az += w0 * x0.z; aw += w0 * x0.w;
        ax += w1 * x1.x; ay += w1 * x1.y; az += w1 * x1.z; aw += w1 * x1.w;
        ax += w2 * x2.x; ay += w2 * x2.y; az += w2 * x2.z; aw += w2 * x2.w;
        ax += w3 * x3.x; ay += w3 * x3.y; az += w3 * x3.z; aw += w3 * x3.w;
    }
    for (; e < end; e++) {
        int s0 = g_srcsorted[e];
        float w0 = g_outnorm[s0];
        float4 x0 = *(const float4*)(h + (size_t)s0 * DD + lane * 4);
        ax += w0 * x0.x; ay += w0 * x0.y; az += w0 * x0.z; aw += w0 * x0.w;
    }
    float s = g_innorm[gw];
    float4 r = make_float4(ax * s, ay * s, az * s, aw * s);
    *(float4*)(g_agg + (size_t)gw * DD + lane * 4) = r;
}

// ---------------- SGEMM: C[M,128] = A[M,128] @ W[128,128] + b, optional relu ----------
#define LDSA 132

__global__ void gemm_kernel(const float* __restrict__ A, const float* __restrict__ W,
                            const float* __restrict__ bias, float* __restrict__ C,
                            int M, int doRelu) {
    extern __shared__ float smem[];
    float* As = smem;               // k-major: As[k*LDSA + m]
    float* Bs = smem + 128 * LDSA;  // row-major: Bs[k*128 + n]
    int tid = threadIdx.x;
    int blockM = blockIdx.x * 128;

    {
        int m  = tid >> 1;
        int kh = (tid & 1) * 64;
        int gm = blockM + m;
        bool valid = gm < M;
        const float4* arow = (const float4*)(A + (size_t)gm * DD + kh);
        #pragma unroll
        for (int j = 0; j < 16; j++) {
            float4 v = valid ? arow[j] : make_float4(0.f, 0.f, 0.f, 0.f);
            int k = kh + j * 4;
            As[(k + 0) * LDSA + m] = v.x;
            As[(k + 1) * LDSA + m] = v.y;
            As[(k + 2) * LDSA + m] = v.z;
            As[(k + 3) * LDSA + m] = v.w;
        }
    }
    {
        int nq = tid & 31;
        int kg = tid >> 5;
        #pragma unroll
        for (int r = 0; r < 16; r++) {
            int k = kg * 16 + r;
            *(float4*)(Bs + k * 128 + nq * 4) = *(const float4*)(W + k * 128 + nq * 4);
        }
    }
    __syncthreads();

    int tx = tid & 15, ty = tid >> 4;
    int mBase = ty * 8, nBase = tx * 8;

    unsigned long long acc[8][4];
    const unsigned long long z = pack2(0.f, 0.f);
    #pragma unroll
    for (int i = 0; i < 8; i++)
        #pragma unroll
        for (int jp = 0; jp < 4; jp++) acc[i][jp] = z;

    #pragma unroll 4
    for (int k = 0; k < 128; k++) {
        float4 a0 = *(const float4*)(As + k * LDSA + mBase);
        float4 a1 = *(const float4*)(As + k * LDSA + mBase + 4);
        float4 b0 = *(const float4*)(Bs + k * 128 + nBase);
        float4 b1 = *(const float4*)(Bs + k * 128 + nBase + 4);

        unsigned long long bp[4];
        bp[0] = pack2(b0.x, b0.y);
        bp[1] = pack2(b0.z, b0.w);
        bp[2] = pack2(b1.x, b1.y);
        bp[3] = pack2(b1.z, b1.w);

        float a[8] = {a0.x, a0.y, a0.z, a0.w, a1.x, a1.y, a1.z, a1.w};
        #pragma unroll
        for (int i = 0; i < 8; i++) {
            unsigned long long aa = bcast2(a[i]);
            #pragma unroll
            for (int jp = 0; jp < 4; jp++)
                ffma2(acc[i][jp], aa, bp[jp]);
        }
    }

    float bv[8];
    #pragma unroll
    for (int j = 0; j < 8; j++) bv[j] = bias[nBase + j];

    #pragma unroll
    for (int i = 0; i < 8; i++) {
        int gm = blockM + mBase + i;
        if (gm < M) {
            float o[8];
            #pragma unroll
            for (int jp = 0; jp < 4; jp++) {
                float x, y;
                unpack2(acc[i][jp], x, y);
                o[jp * 2]     = x + bv[jp * 2];
                o[jp * 2 + 1] = y + bv[jp * 2 + 1];
            }
            if (doRelu) {
                #pragma unroll
                for (int j = 0; j < 8; j++) o[j] = fmaxf(o[j], 0.f);
            }
            *(float4*)(C + (size_t)gm * DD + nBase)     = make_float4(o[0], o[1], o[2], o[3]);
            *(float4*)(C + (size_t)gm * DD + nBase + 4) = make_float4(o[4], o[5], o[6], o[7]);
        }
    }
}

// ---------------- launch ----------------
extern "C" void kernel_launch(void* const* d_in, const int* in_sizes, int n_in,
                              void* d_out, int out_size) {
    const float* h   = (const float*)d_in[0];
    const float* e   = (const float*)d_in[1];
    const int*   src = (const int*)  d_in[2];
    const int*   dst = (const int*)  d_in[3];
    const float* Ws  = (const float*)d_in[4];
    const float* bs  = (const float*)d_in[5];
    float* out = (float*)d_out;

    // Side stream + events: thin streaming copy runs parallel to compute.
    static cudaStream_t s_side = nullptr;
    static cudaEvent_t  s_fork = nullptr, s_join = nullptr;
    if (!s_side) {
        cudaStreamCreateWithFlags(&s_side, cudaStreamNonBlocking);
        cudaEventCreateWithFlags(&s_fork, cudaEventDisableTiming);
        cudaEventCreateWithFlags(&s_join, cudaEventDisableTiming);
    }

    size_t eElems = (size_t)in_sizes[1];
    int n4 = (int)(eElems / 4);
    const int copyBlocks = 148;          // thin: ~1 block/SM, 12.5% thread slots
    bool overlapped = false;
    if (s_side && s_fork && s_join) {
        if (cudaEventRecord(s_fork, 0) == cudaSuccess &&
            cudaStreamWaitEvent(s_side, s_fork, 0) == cudaSuccess) {
            copy_kernel<<<copyBlocks, 256, 0, s_side>>>(
                (const float4*)e, (float4*)(out + (size_t)NN * DD), n4);
            cudaEventRecord(s_join, s_side);
            overlapped = true;
        }
    }
    if (!overlapped) {
        copy_kernel<<<copyBlocks * 6, 256>>>(
            (const float4*)e, (float4*)(out + (size_t)NN * DD), n4);
    }

    const int nb = (NN + 255) / 256;
    const int eb = (EE + 255) / 256;
    zero_kernel<<<nb, 256>>>();
    deg_kernel<<<eb, 256>>>(src, dst);
    norm_kernel<<<nb, 256>>>();
    scanA_kernel<<<SCAN_B, SCAN_T>>>();
    scanB_kernel<<<1, 32>>>();
    scanC_kernel<<<SCAN_B, SCAN_T>>>();
    scatter_kernel<<<eb, 256>>>(src, dst);

    float *agg, *b0, *b1;
    cudaGetSymbolAddress((void**)&agg, g_agg);
    cudaGetSymbolAddress((void**)&b0,  g_buf0);
    cudaGetSymbolAddress((void**)&b1,  g_buf1);

    const int SMEM = (128 * LDSA + 128 * 128) * (int)sizeof(float);
    cudaFuncSetAttribute(gemm_kernel, cudaFuncAttributeMaxDynamicSharedMemorySize, SMEM);

    const int aggBlocks  = (NN * 32 + 255) / 256;
    const int gemmBlocks = (NN + 127) / 128;

    // layer 0
    agg_kernel<<<aggBlocks, 256>>>(h);
    gemm_kernel<<<gemmBlocks, 256, SMEM>>>(agg, Ws,               bs,          b0, NN, 1);
    // layer 1
    agg_kernel<<<aggBlocks, 256>>>(b0);
    gemm_kernel<<<gemmBlocks, 256, SMEM>>>(agg, Ws + DD * DD,     bs + DD,     b1, NN, 1);
    // layer 2 (no relu), write straight into d_out
    agg_kernel<<<aggBlocks, 256>>>(b1);
    gemm_kernel<<<gemmBlocks, 256, SMEM>>>(agg, Ws + 2 * DD * DD, bs + 2 * DD, out, NN, 0);

    if (overlapped) cudaStreamWaitEvent(0, s_join, 0);
}